// round 1
// baseline (speedup 1.0000x reference)
#include <cuda_runtime.h>
#include <cuda_bf16.h>
#include <math.h>

// Problem constants
#define B_  32
#define T_  4096
#define D_  1024
#define E_  128
#define K_  16
#define KEV_ 8
#define DK_ (D_ + E_)          // 1152
#define M_  (B_ * K_)          // 512 rows

// Output section offsets (float32, concatenated in reference return order)
#define OFF_ENTRIES 0
#define OFF_VALID   (B_ * K_ * D_)                 // 524288
#define OFF_TIMES   (OFF_VALID + B_ * K_)          // 524800
#define OFF_HOLDER  (OFF_TIMES + B_ * K_)          // 525312
#define OUT_TOTAL   (OFF_HOLDER + B_ * K_ * E_)    // 590848

// Scratch (static device globals: allocation-free per harness rules)
__device__ int   g_chosen[M_];
__device__ int   g_valid[M_];
__device__ float g_raw[(long)M_ * DK_];

// ---------------------------------------------------------------------------
// Kernel 1: per-batch top-8 (tie -> smaller index), merge with uniform grid,
// sort/unique, take first K_=16. Writes g_chosen/g_valid + times/valid output.
// ---------------------------------------------------------------------------
__global__ void topk_choose_kernel(const float* __restrict__ scores,
                                   float* __restrict__ out, int out_size) {
    __shared__ float s[T_];
    __shared__ unsigned long long red[256];
    __shared__ int ev[KEV_];

    const int b = blockIdx.x;
    const int tid = threadIdx.x;
    const float* sb = scores + (long)b * T_;

    for (int i = tid; i < T_; i += 256) s[i] = sb[i];
    __syncthreads();

    for (int pick = 0; pick < KEV_; ++pick) {
        unsigned long long best = 0ULL;
        for (int i = tid; i < T_; i += 256) {
            float v = s[i];
            unsigned u = __float_as_uint(v);
            u = (u & 0x80000000u) ? ~u : (u | 0x80000000u);  // monotonic map
            unsigned long long key =
                ((unsigned long long)u << 32) | (unsigned)(T_ - 1 - i);
            if (key > best) best = key;
        }
        red[tid] = best;
        __syncthreads();
        for (int off = 128; off > 0; off >>= 1) {
            if (tid < off && red[tid + off] > red[tid]) red[tid] = red[tid + off];
            __syncthreads();
        }
        if (tid == 0) {
            int idx = (T_ - 1) - (int)(red[0] & 0xFFFFFFFFu);
            ev[pick] = idx;
            s[idx] = __int_as_float(0xff800000);  // -inf, exclude
        }
        __syncthreads();
    }

    if (tid == 0) {
        int c[KEV_ + K_];
        for (int i = 0; i < KEV_; ++i) c[i] = ev[i];
        // uniform grid: linspace(0, T-1, K) computed in fp32 then truncated
        float step = (float)(T_ - 1) / (float)(K_ - 1);
        for (int i = 0; i < K_; ++i) c[KEV_ + i] = (int)((float)i * step);
        // insertion sort 24 ints
        for (int i = 1; i < KEV_ + K_; ++i) {
            int v = c[i], j = i - 1;
            while (j >= 0 && c[j] > v) { c[j + 1] = c[j]; --j; }
            c[j + 1] = v;
        }
        // unique
        int u[KEV_ + K_]; int n = 0;
        for (int i = 0; i < KEV_ + K_; ++i)
            if (i == 0 || c[i] != c[i - 1]) u[n++] = c[i];
        int nv = n < K_ ? n : K_;
        for (int k = 0; k < K_; ++k) {
            int ch = (k < n) ? u[k] : 0;
            int vd = (k < nv) ? 1 : 0;
            g_chosen[b * K_ + k] = ch;
            g_valid[b * K_ + k]  = vd;
            if (out_size >= OUT_TOTAL) {
                out[OFF_VALID + b * K_ + k] = (float)vd;
                out[OFF_TIMES + b * K_ + k] = (float)(ch * vd);
            }
        }
    }
}

// ---------------------------------------------------------------------------
// Kernel 2: per (b,k) row — gather state row, softmax holder logits, build
// raw[row, 0:1024]=state, raw[row,1024:1152]=softmax. Also writes holder_out.
// 512 blocks x 128 threads.
// ---------------------------------------------------------------------------
__global__ void build_raw_kernel(const float* __restrict__ state,
                                 const float* __restrict__ hl,
                                 float* __restrict__ out, int out_size) {
    const int row = blockIdx.x;          // 0..511
    const int b = row >> 4;
    const int tid = threadIdx.x;         // 0..127
    const int idx = g_chosen[row];
    const float vf = (float)g_valid[row];

    __shared__ float sm[E_];

    float x = hl[((long)b * T_ + idx) * E_ + tid];
    if (out_size >= OUT_TOTAL)
        out[OFF_HOLDER + (long)row * E_ + tid] = x * vf;

    // softmax over 128 elements
    sm[tid] = x;
    __syncthreads();
    for (int off = 64; off > 0; off >>= 1) {
        if (tid < off) sm[tid] = fmaxf(sm[tid], sm[tid + off]);
        __syncthreads();
    }
    float mx = sm[0];
    __syncthreads();
    float e = expf(x - mx);
    sm[tid] = e;
    __syncthreads();
    for (int off = 64; off > 0; off >>= 1) {
        if (tid < off) sm[tid] += sm[tid + off];
        __syncthreads();
    }
    float inv = 1.0f / sm[0];

    float* rawrow = g_raw + (long)row * DK_;
    rawrow[D_ + tid] = e * inv;

    // copy state row (1024 floats = 256 float4), 128 threads x 2
    const float4* src = (const float4*)(state + ((long)b * T_ + idx) * D_);
    float4* dst = (float4*)rawrow;
    dst[tid]       = src[tid];
    dst[tid + 128] = src[tid + 128];
}

// ---------------------------------------------------------------------------
// Kernel 3: GEMM  C[512,1024] = raw[512,1152] * W[1024,1152]^T  + bias + te
// Tiled: BM=BN=64, BK=16, 256 threads, 4x4 microtile, k-major smem tiles.
// ---------------------------------------------------------------------------
#define BM 64
#define BN 64
#define BK 16
#define SPAD 68   // padded row length (floats) for smem tiles

__global__ __launch_bounds__(256)
void gemm_epilogue_kernel(const float* __restrict__ W,
                          const float* __restrict__ bias,
                          const float* __restrict__ time_table,
                          float* __restrict__ out) {
    __shared__ float As[BK][SPAD];
    __shared__ float Bs[BK][SPAD];

    const int bm = blockIdx.y * BM;
    const int bn = blockIdx.x * BN;
    const int tid = threadIdx.x;
    const int tx = tid & 15;     // 0..15 -> n subtile
    const int ty = tid >> 4;     // 0..15 -> m subtile

    // global load mapping: each thread loads one float4 of A and one of W
    const int lm = tid >> 2;           // 0..63 : row within tile
    const int lk = (tid & 3) * 4;      // 0,4,8,12 : k offset within tile

    float acc[4][4];
#pragma unroll
    for (int i = 0; i < 4; ++i)
#pragma unroll
        for (int j = 0; j < 4; ++j) acc[i][j] = 0.f;

    for (int k0 = 0; k0 < DK_; k0 += BK) {
        float4 av = *(const float4*)(g_raw + (long)(bm + lm) * DK_ + k0 + lk);
        float4 wv = *(const float4*)(W + (long)(bn + lm) * DK_ + k0 + lk);
        As[lk + 0][lm] = av.x; As[lk + 1][lm] = av.y;
        As[lk + 2][lm] = av.z; As[lk + 3][lm] = av.w;
        Bs[lk + 0][lm] = wv.x; Bs[lk + 1][lm] = wv.y;
        Bs[lk + 2][lm] = wv.z; Bs[lk + 3][lm] = wv.w;
        __syncthreads();

#pragma unroll
        for (int kk = 0; kk < BK; ++kk) {
            float4 a = *(const float4*)&As[kk][ty * 4];
            float4 bq = *(const float4*)&Bs[kk][tx * 4];
            float ar[4] = {a.x, a.y, a.z, a.w};
            float br[4] = {bq.x, bq.y, bq.z, bq.w};
#pragma unroll
            for (int i = 0; i < 4; ++i)
#pragma unroll
                for (int j = 0; j < 4; ++j)
                    acc[i][j] = fmaf(ar[i], br[j], acc[i][j]);
        }
        __syncthreads();
    }

    // epilogue: + bias + time_table[min(chosen,511)], * valid
#pragma unroll
    for (int i = 0; i < 4; ++i) {
        int m = bm + ty * 4 + i;
        int tt = g_chosen[m];
        if (tt > 511) tt = 511;
        if (tt < 0) tt = 0;
        float vf = (float)g_valid[m];
        const float* te = time_table + (long)tt * D_;
#pragma unroll
        for (int j = 0; j < 4; ++j) {
            int n = bn + tx * 4 + j;
            out[OFF_ENTRIES + (long)m * D_ + n] =
                (acc[i][j] + bias[n] + te[n]) * vf;
        }
    }
}

// ---------------------------------------------------------------------------
// Launch
// Inputs (metadata order): state_seq, holder_logits, event_scores, W, b, time_table
// ---------------------------------------------------------------------------
extern "C" void kernel_launch(void* const* d_in, const int* in_sizes, int n_in,
                              void* d_out, int out_size) {
    const float* state  = (const float*)d_in[0];
    const float* hl     = (const float*)d_in[1];
    const float* scores = (const float*)d_in[2];
    const float* W      = (const float*)d_in[3];
    const float* bias   = (const float*)d_in[4];
    const float* ttab   = (const float*)d_in[5];
    float* out = (float*)d_out;

    topk_choose_kernel<<<B_, 256>>>(scores, out, out_size);
    build_raw_kernel<<<M_, 128>>>(state, hl, out, out_size);
    dim3 grid(D_ / BN, M_ / BM);
    gemm_epilogue_kernel<<<grid, 256>>>(W, bias, ttab, out);
}

// round 3
// speedup vs baseline: 1.8063x; 1.8063x over previous
#include <cuda_runtime.h>
#include <cuda_bf16.h>
#include <math.h>
#include <cstdint>

// Problem constants
#define B_  32
#define T_  4096
#define D_  1024
#define E_  128
#define K_  16
#define KEV_ 8
#define DK_ (D_ + E_)          // 1152
#define M_  (B_ * K_)          // 512 rows

// Output section offsets (float32, reference return order)
#define OFF_ENTRIES 0
#define OFF_VALID   (B_ * K_ * D_)                 // 524288
#define OFF_TIMES   (OFF_VALID + B_ * K_)          // 524800
#define OFF_HOLDER  (OFF_TIMES + B_ * K_)          // 525312
#define OUT_TOTAL   (OFF_HOLDER + B_ * K_ * E_)    // 590848

// Scratch: split-bf16 planes for A (gathered raw) and B (W)
__device__ int            g_chosen[M_];
__device__ int            g_valid[M_];
__device__ __nv_bfloat16  g_Ahi[(long)M_ * DK_];
__device__ __nv_bfloat16  g_Alo[(long)M_ * DK_];
__device__ __nv_bfloat16  g_Whi[(long)D_ * DK_];
__device__ __nv_bfloat16  g_Wlo[(long)D_ * DK_];

// ---------------------------------------------------------------------------
// small helpers
// ---------------------------------------------------------------------------
__device__ __forceinline__ void split4(float4 v, uint2& hi, uint2& lo) {
    __nv_bfloat16 h0 = __float2bfloat16_rn(v.x);
    __nv_bfloat16 h1 = __float2bfloat16_rn(v.y);
    __nv_bfloat16 h2 = __float2bfloat16_rn(v.z);
    __nv_bfloat16 h3 = __float2bfloat16_rn(v.w);
    __nv_bfloat16 l0 = __float2bfloat16_rn(v.x - __bfloat162float(h0));
    __nv_bfloat16 l1 = __float2bfloat16_rn(v.y - __bfloat162float(h1));
    __nv_bfloat16 l2 = __float2bfloat16_rn(v.z - __bfloat162float(h2));
    __nv_bfloat16 l3 = __float2bfloat16_rn(v.w - __bfloat162float(h3));
    __nv_bfloat162 H01, H23, L01, L23;
    H01.x = h0; H01.y = h1; H23.x = h2; H23.y = h3;
    L01.x = l0; L01.y = l1; L23.x = l2; L23.y = l3;
    hi = make_uint2(*(uint32_t*)&H01, *(uint32_t*)&H23);
    lo = make_uint2(*(uint32_t*)&L01, *(uint32_t*)&L23);
}

__device__ __forceinline__ void mma_bf16(float* c, const uint32_t* a,
                                         const uint32_t* b) {
    asm volatile(
        "mma.sync.aligned.m16n8k16.row.col.f32.bf16.bf16.f32 "
        "{%0,%1,%2,%3}, {%4,%5,%6,%7}, {%8,%9}, {%0,%1,%2,%3};"
        : "+f"(c[0]), "+f"(c[1]), "+f"(c[2]), "+f"(c[3])
        : "r"(a[0]), "r"(a[1]), "r"(a[2]), "r"(a[3]),
          "r"(b[0]), "r"(b[1]));
}

__device__ __forceinline__ void cp16(uint32_t smem_dst, const void* gsrc) {
    asm volatile("cp.async.cg.shared.global [%0], [%1], 16;"
                 :: "r"(smem_dst),
                    "l"((unsigned long long)__cvta_generic_to_global(gsrc)));
}
#define CP_COMMIT() asm volatile("cp.async.commit_group;")
#define CP_WAIT(n)  asm volatile("cp.async.wait_group %0;" :: "n"(n))

// ---------------------------------------------------------------------------
// Kernel 1: single-pass top-8 per batch + merge with uniform grid.
// ---------------------------------------------------------------------------
__device__ __forceinline__ unsigned long long score_key(float v, int i) {
    unsigned u = __float_as_uint(v);
    u = (u & 0x80000000u) ? ~u : (u | 0x80000000u);
    return ((unsigned long long)u << 32) | (unsigned)(T_ - 1 - i);
}

__global__ void topk_choose_kernel(const float* __restrict__ scores,
                                   float* __restrict__ out, int out_size) {
    __shared__ unsigned long long wtop[8][KEV_];
    __shared__ int ev[KEV_];

    const int b = blockIdx.x;
    const int tid = threadIdx.x;        // 256 threads
    const int lane = tid & 31, warp = tid >> 5;
    const float* sb = scores + (long)b * T_;

    unsigned long long list[KEV_];
#pragma unroll
    for (int k = 0; k < KEV_; ++k) list[k] = 0ULL;
#pragma unroll
    for (int j = 0; j < T_ / 256; ++j) {
        int i = tid + j * 256;
        unsigned long long key = score_key(sb[i], i);
        if (key > list[KEV_ - 1]) {
            int p = KEV_ - 1;
            while (p > 0 && list[p - 1] < key) { list[p] = list[p - 1]; --p; }
            list[p] = key;
        }
    }
    int ptr = 0;
#pragma unroll
    for (int pick = 0; pick < KEV_; ++pick) {
        unsigned long long cand = (ptr < KEV_) ? list[ptr] : 0ULL;
        unsigned long long m = cand;
#pragma unroll
        for (int off = 16; off > 0; off >>= 1) {
            unsigned long long o = __shfl_xor_sync(0xffffffffu, m, off);
            if (o > m) m = o;
        }
        if (cand == m && cand != 0ULL) ++ptr;
        if (lane == 0) wtop[warp][pick] = m;
    }
    __syncthreads();
    if (warp == 0) {
        unsigned long long mylist[KEV_];
#pragma unroll
        for (int k = 0; k < KEV_; ++k)
            mylist[k] = (lane < 8) ? wtop[lane][k] : 0ULL;
        int p2 = 0;
#pragma unroll
        for (int pick = 0; pick < KEV_; ++pick) {
            unsigned long long cand = (lane < 8 && p2 < KEV_) ? mylist[p2] : 0ULL;
            unsigned long long m = cand;
#pragma unroll
            for (int off = 16; off > 0; off >>= 1) {
                unsigned long long o = __shfl_xor_sync(0xffffffffu, m, off);
                if (o > m) m = o;
            }
            if (cand == m && cand != 0ULL) ++p2;
            if (lane == 0) ev[pick] = (T_ - 1) - (int)(m & 0xFFFFFFFFu);
        }
    }
    __syncthreads();

    if (tid == 0) {
        int c[KEV_ + K_];
        for (int i = 0; i < KEV_; ++i) c[i] = ev[i];
        float step = (float)(T_ - 1) / (float)(K_ - 1);
        for (int i = 0; i < K_; ++i) c[KEV_ + i] = (int)((float)i * step);
        for (int i = 1; i < KEV_ + K_; ++i) {
            int v = c[i], j = i - 1;
            while (j >= 0 && c[j] > v) { c[j + 1] = c[j]; --j; }
            c[j + 1] = v;
        }
        int u[KEV_ + K_]; int n = 0;
        for (int i = 0; i < KEV_ + K_; ++i)
            if (i == 0 || c[i] != c[i - 1]) u[n++] = c[i];
        int nv = n < K_ ? n : K_;
        for (int k = 0; k < K_; ++k) {
            int ch = (k < n) ? u[k] : 0;
            int vd = (k < nv) ? 1 : 0;
            g_chosen[b * K_ + k] = ch;
            g_valid[b * K_ + k]  = vd;
            if (out_size >= OUT_TOTAL) {
                out[OFF_VALID + b * K_ + k] = (float)vd;
                out[OFF_TIMES + b * K_ + k] = (float)(ch * vd);
            }
        }
    }
}

// ---------------------------------------------------------------------------
// Kernel 2: pack W -> split bf16 planes (hi, lo)
// ---------------------------------------------------------------------------
__global__ void pack_w_kernel(const float* __restrict__ W) {
    long i = (long)blockIdx.x * 256 + threadIdx.x;   // float4 index
    float4 v = ((const float4*)W)[i];
    uint2 hi, lo;
    split4(v, hi, lo);
    *(uint2*)(g_Whi + i * 4) = hi;
    *(uint2*)(g_Wlo + i * 4) = lo;
}

// ---------------------------------------------------------------------------
// Kernel 3: gather state row + softmax -> split bf16 A planes; holder_out.
// ---------------------------------------------------------------------------
__global__ void build_raw_kernel(const float* __restrict__ state,
                                 const float* __restrict__ hl,
                                 float* __restrict__ out, int out_size) {
    const int row = blockIdx.x;          // 0..511
    const int b = row >> 4;
    const int tid = threadIdx.x;         // 0..127
    const int idx = g_chosen[row];
    const float vf = (float)g_valid[row];

    __shared__ float sm[E_];

    float x = hl[((long)b * T_ + idx) * E_ + tid];
    if (out_size >= OUT_TOTAL)
        out[OFF_HOLDER + (long)row * E_ + tid] = x * vf;

    sm[tid] = x;
    __syncthreads();
    for (int off = 64; off > 0; off >>= 1) {
        if (tid < off) sm[tid] = fmaxf(sm[tid], sm[tid + off]);
        __syncthreads();
    }
    float mx = sm[0];
    __syncthreads();
    float e = expf(x - mx);
    sm[tid] = e;
    __syncthreads();
    for (int off = 64; off > 0; off >>= 1) {
        if (tid < off) sm[tid] += sm[tid + off];
        __syncthreads();
    }
    float p = e / sm[0];

    __nv_bfloat16* hi = g_Ahi + (long)row * DK_;
    __nv_bfloat16* lo = g_Alo + (long)row * DK_;

    __nv_bfloat16 ph = __float2bfloat16_rn(p);
    hi[D_ + tid] = ph;
    lo[D_ + tid] = __float2bfloat16_rn(p - __bfloat162float(ph));

    const float4* src = (const float4*)(state + ((long)b * T_ + idx) * D_);
#pragma unroll
    for (int t = 0; t < 2; ++t) {
        int q = tid + t * 128;           // float4 index within row
        float4 v = src[q];
        uint2 h2, l2;
        split4(v, h2, l2);
        *(uint2*)(hi + q * 4) = h2;
        *(uint2*)(lo + q * 4) = l2;
    }
}

// ---------------------------------------------------------------------------
// Kernel 4: HMMA split-bf16 GEMM
//   C[512,1024] = raw[512,1152] @ W[1024,1152]^T, epilogue fused.
// BM=BN=64, BK=32, 256 threads (8 warps, 2x4), warp tile 32x16,
// per warp 2x2 m16n8 tiles, 3 accumulation passes (hh, hl, lh).
// ---------------------------------------------------------------------------
#define GBM 64
#define GBN 64
#define GBK 32
#define NSTAGE (DK_ / GBK)    // 36
#define PADK 40               // padded k stride (bf16 elems) per smem row
// planes: 0=Ahi 1=Alo 2=Bhi 3=Blo ; each [64][PADK]
#define PLANE_ELEMS (64 * PADK)

__global__ __launch_bounds__(256)
void gemm_hmma_kernel(const float* __restrict__ bias,
                      const float* __restrict__ time_table,
                      float* __restrict__ out) {
    __shared__ __nv_bfloat16 smem[2][4][PLANE_ELEMS];   // 40960 B

    const int tid = threadIdx.x;
    const int lane = tid & 31;
    const int warp = tid >> 5;             // 0..7
    const int warp_m = (warp & 1) * 32;    // 0 or 32
    const int warp_n = (warp >> 1) * 16;   // 0,16,32,48
    const int bm = blockIdx.y * GBM;
    const int bn = blockIdx.x * GBN;

    const int lrow = tid >> 2;             // 0..63
    const int lcq  = tid & 3;              // 16B chunk within 64B row

    // ---- stage loader: 4 cp.async (one 16B chunk per plane) ----
    auto load_stage = [&](int st, int buf) {
        const long k0 = (long)st * GBK;
        const long aoff = (long)(bm + lrow) * DK_ + k0 + lcq * 8;
        const long boff = (long)(bn + lrow) * DK_ + k0 + lcq * 8;
        const int  soff = lrow * PADK + lcq * 8;
        cp16((uint32_t)__cvta_generic_to_shared(&smem[buf][0][soff]), g_Ahi + aoff);
        cp16((uint32_t)__cvta_generic_to_shared(&smem[buf][1][soff]), g_Alo + aoff);
        cp16((uint32_t)__cvta_generic_to_shared(&smem[buf][2][soff]), g_Whi + boff);
        cp16((uint32_t)__cvta_generic_to_shared(&smem[buf][3][soff]), g_Wlo + boff);
        CP_COMMIT();
    };

    float acc[2][2][4];
#pragma unroll
    for (int i = 0; i < 2; ++i)
#pragma unroll
        for (int j = 0; j < 2; ++j)
#pragma unroll
            for (int q = 0; q < 4; ++q) acc[i][j][q] = 0.f;

    load_stage(0, 0);
    load_stage(1, 1);

    const int r = lane >> 2;
    const int kq = (lane & 3) * 2;

    for (int st = 0; st < NSTAGE; ++st) {
        const int buf = st & 1;
        if (st + 1 < NSTAGE) { CP_WAIT(1); } else { CP_WAIT(0); }
        __syncthreads();

#pragma unroll
        for (int ks = 0; ks < 2; ++ks) {
            const int kb = ks * 16 + kq;
            uint32_t ahi[2][4], alo[2][4], bhi[2][2], blo[2][2];
#pragma unroll
            for (int mt = 0; mt < 2; ++mt) {
                const int rb = (warp_m + mt * 16 + r) * PADK;
                const __nv_bfloat16* pa = smem[buf][0];
                const __nv_bfloat16* pl = smem[buf][1];
                ahi[mt][0] = *(const uint32_t*)(pa + rb + kb);
                ahi[mt][1] = *(const uint32_t*)(pa + rb + 8 * PADK + kb);
                ahi[mt][2] = *(const uint32_t*)(pa + rb + kb + 8);
                ahi[mt][3] = *(const uint32_t*)(pa + rb + 8 * PADK + kb + 8);
                alo[mt][0] = *(const uint32_t*)(pl + rb + kb);
                alo[mt][1] = *(const uint32_t*)(pl + rb + 8 * PADK + kb);
                alo[mt][2] = *(const uint32_t*)(pl + rb + kb + 8);
                alo[mt][3] = *(const uint32_t*)(pl + rb + 8 * PADK + kb + 8);
            }
#pragma unroll
            for (int nt = 0; nt < 2; ++nt) {
                const int nb = (warp_n + nt * 8 + r) * PADK;
                const __nv_bfloat16* pb = smem[buf][2];
                const __nv_bfloat16* pl = smem[buf][3];
                bhi[nt][0] = *(const uint32_t*)(pb + nb + kb);
                bhi[nt][1] = *(const uint32_t*)(pb + nb + kb + 8);
                blo[nt][0] = *(const uint32_t*)(pl + nb + kb);
                blo[nt][1] = *(const uint32_t*)(pl + nb + kb + 8);
            }
#pragma unroll
            for (int mt = 0; mt < 2; ++mt)
#pragma unroll
                for (int nt = 0; nt < 2; ++nt) {
                    mma_bf16(acc[mt][nt], ahi[mt], bhi[nt]);
                    mma_bf16(acc[mt][nt], ahi[mt], blo[nt]);
                    mma_bf16(acc[mt][nt], alo[mt], bhi[nt]);
                }
        }
        __syncthreads();
        if (st + 2 < NSTAGE) load_stage(st + 2, buf);
    }

    // ---- epilogue: + bias + time_table[clip(chosen,0,511)], * valid ----
#pragma unroll
    for (int mt = 0; mt < 2; ++mt) {
#pragma unroll
        for (int half = 0; half < 2; ++half) {
            const int m = bm + warp_m + mt * 16 + r + half * 8;
            int tt = g_chosen[m];
            tt = tt < 0 ? 0 : (tt > 511 ? 511 : tt);
            const float vf = (float)g_valid[m];
            const float* te = time_table + (long)tt * D_;
            float* op = out + OFF_ENTRIES + (long)m * D_;
#pragma unroll
            for (int nt = 0; nt < 2; ++nt) {
                const int n0 = bn + warp_n + nt * 8 + kq;
                const float c0 = acc[mt][nt][half * 2 + 0];
                const float c1 = acc[mt][nt][half * 2 + 1];
                float2 o;
                o.x = (c0 + bias[n0]     + te[n0])     * vf;
                o.y = (c1 + bias[n0 + 1] + te[n0 + 1]) * vf;
                *(float2*)(op + n0) = o;
            }
        }
    }
}

// ---------------------------------------------------------------------------
// Launch. Inputs: state_seq, holder_logits, event_scores, W, b, time_table
// ---------------------------------------------------------------------------
extern "C" void kernel_launch(void* const* d_in, const int* in_sizes, int n_in,
                              void* d_out, int out_size) {
    const float* state  = (const float*)d_in[0];
    const float* hl     = (const float*)d_in[1];
    const float* scores = (const float*)d_in[2];
    const float* W      = (const float*)d_in[3];
    const float* bias   = (const float*)d_in[4];
    const float* ttab   = (const float*)d_in[5];
    float* out = (float*)d_out;

    topk_choose_kernel<<<B_, 256>>>(scores, out, out_size);
    pack_w_kernel<<<(D_ * DK_ / 4) / 256, 256>>>(W);
    build_raw_kernel<<<M_, 128>>>(state, hl, out, out_size);
    dim3 grid(D_ / GBN, M_ / GBM);   // (16, 8) = 128 CTAs
    gemm_hmma_kernel<<<grid, 256>>>(bias, ttab, out);
}